// round 5
// baseline (speedup 1.0000x reference)
#include <cuda_runtime.h>
#include <cuda_fp16.h>
#include <cuda_bf16.h>
#include <cstdint>

// Problem constants
#define NB   128          // batch
#define NT   64           // max timesteps
#define NE   512          // embedding dim
#define NH   1024         // hidden dim
#define N3H  3072         // 3*H (gate order r,z,n)
#define NBT  (NB*NT)      // 8192 rows for xgates GEMM

// k_recur geometry: each CTA owns 32 units x 32 batch rows
#define UCNT   32                 // hidden units per CTA
#define BROWS  32                 // batch rows per CTA
#define SWROWS 96                 // 3 gates * 32 units
#define SWW    516                // w_hh row stride (512 words = 1024 fp16) + 4 pad
#define SHW    36                 // h stage row stride: 32 words (64 fp16) + 4 pad
#define NSTG   6                  // cp.async ring depth
#define STGW   (BROWS * SHW)      // words per stage (1152)

// Scratch (device globals; no runtime allocation allowed)
__device__ float g_xg[(size_t)NT * NB * N3H];              // [t][b][3H]
__device__ __align__(16) __half g_h16[2][NB * NH];         // fp16 h exchange (L2)
__device__ float g_final[NB * NH];                         // h at t == len-1
__device__ unsigned g_flag[4][32];                         // [bq][ug] steps done

// ---------------------------------------------------------------------------
// helpers
// ---------------------------------------------------------------------------
__device__ __forceinline__ void mma_tf32(float c[4], const uint32_t a[4],
                                         uint32_t b0, uint32_t b1) {
    asm volatile(
        "mma.sync.aligned.m16n8k8.row.col.f32.tf32.tf32.f32 "
        "{%0,%1,%2,%3}, {%4,%5,%6,%7}, {%8,%9}, {%0,%1,%2,%3};"
        : "+f"(c[0]), "+f"(c[1]), "+f"(c[2]), "+f"(c[3])
        : "r"(a[0]), "r"(a[1]), "r"(a[2]), "r"(a[3]), "r"(b0), "r"(b1));
}

__device__ __forceinline__ void mma_f16(float c[4], const uint32_t a[4],
                                        uint32_t b0, uint32_t b1) {
    asm volatile(
        "mma.sync.aligned.m16n8k16.row.col.f32.f16.f16.f32 "
        "{%0,%1,%2,%3}, {%4,%5,%6,%7}, {%8,%9}, {%0,%1,%2,%3};"
        : "+f"(c[0]), "+f"(c[1]), "+f"(c[2]), "+f"(c[3])
        : "r"(a[0]), "r"(a[1]), "r"(a[2]), "r"(a[3]), "r"(b0), "r"(b1));
}

__device__ __forceinline__ void cp_async16(uint32_t saddr, const void* gaddr) {
    asm volatile("cp.async.cg.shared.global [%0], [%1], 16;"
                 :: "r"(saddr), "l"(gaddr));
}
__device__ __forceinline__ void cp_commit() {
    asm volatile("cp.async.commit_group;");
}
template <int N>
__device__ __forceinline__ void cp_wait() {
    asm volatile("cp.async.wait_group %0;" :: "n"(N));
}

__device__ __forceinline__ unsigned ld_acq(const unsigned* p) {
    unsigned v;
    asm volatile("ld.acquire.gpu.global.u32 %0, [%1];" : "=r"(v) : "l"(p));
    return v;
}
__device__ __forceinline__ void st_rel(unsigned* p, unsigned v) {
    asm volatile("st.release.gpu.global.u32 [%0], %1;" :: "l"(p), "r"(v));
}

// ---------------------------------------------------------------------------
// k_init: zero h16[0] and flags
// ---------------------------------------------------------------------------
__global__ void k_init() {
    int i = blockIdx.x * blockDim.x + threadIdx.x;
    if (i < NB * NH) g_h16[0][i] = __float2half(0.0f);
    if (i < 128) g_flag[i & 3][i >> 2] = 0u;
}

// ---------------------------------------------------------------------------
// k_xgates: xg[t][b][n] = emb_table[sent[b,t]] . w_ih[n] + b_ih[n]
// GEMM M=8192, N=3072, K=512. Tile 128x128, KC=32.
// cp.async double-buffered fp32 tiles; raw fp32 bits fed as tf32 (truncation).
// ---------------------------------------------------------------------------
__global__ void __launch_bounds__(256, 2)
k_xgates(const int* __restrict__ sent, const float* __restrict__ emb,
         const float* __restrict__ w_ih, const float* __restrict__ b_ih) {
    extern __shared__ uint32_t xsm[];
    uint32_t* sA = xsm;
    uint32_t* sB = xsm + 2 * 128 * 36;

    const int tid  = threadIdx.x;
    const int wid  = tid >> 5;
    const int lane = tid & 31;
    const int g    = lane >> 2;
    const int t4   = lane & 3;

    const int m0 = blockIdx.y * 128;
    const int n0 = blockIdx.x * 128;
    const int wm = (wid & 3) * 32;
    const int wn = (wid >> 2) * 64;

    int ldrow[4], ldcol[4], ldtok[4];
#pragma unroll
    for (int p = 0; p < 4; p++) {
        int idx = tid + p * 256;
        ldrow[p] = idx >> 3;
        ldcol[p] = (idx & 7) << 2;
        ldtok[p] = sent[m0 + ldrow[p]];
    }

    float c[2][8][4];
#pragma unroll
    for (int mf = 0; mf < 2; mf++)
#pragma unroll
        for (int nt = 0; nt < 8; nt++)
#pragma unroll
            for (int e = 0; e < 4; e++) c[mf][nt][e] = 0.0f;

#pragma unroll
    for (int p = 0; p < 4; p++) {
        uint32_t sa = (uint32_t)__cvta_generic_to_shared(
            sA + ldrow[p] * 36 + ldcol[p]);
        cp_async16(sa, emb + (size_t)ldtok[p] * NE + ldcol[p]);
        uint32_t sb = (uint32_t)__cvta_generic_to_shared(
            sB + ldrow[p] * 36 + ldcol[p]);
        cp_async16(sb, w_ih + (size_t)(n0 + ldrow[p]) * NE + ldcol[p]);
    }
    cp_commit();

    for (int kt = 0; kt < 16; kt++) {
        const int cur = kt & 1;
        if (kt + 1 < 16) {
            const int nxt = cur ^ 1;
            const int kk = (kt + 1) * 32;
#pragma unroll
            for (int p = 0; p < 4; p++) {
                uint32_t sa = (uint32_t)__cvta_generic_to_shared(
                    sA + nxt * 128 * 36 + ldrow[p] * 36 + ldcol[p]);
                cp_async16(sa, emb + (size_t)ldtok[p] * NE + kk + ldcol[p]);
                uint32_t sb = (uint32_t)__cvta_generic_to_shared(
                    sB + nxt * 128 * 36 + ldrow[p] * 36 + ldcol[p]);
                cp_async16(sb, w_ih + (size_t)(n0 + ldrow[p]) * NE + kk + ldcol[p]);
            }
        }
        cp_commit();
        cp_wait<1>();
        __syncthreads();

        const uint32_t* A = sA + cur * 128 * 36;
        const uint32_t* B = sB + cur * 128 * 36;
#pragma unroll
        for (int k8 = 0; k8 < 32; k8 += 8) {
            uint32_t a[2][4];
#pragma unroll
            for (int mf = 0; mf < 2; mf++) {
                int r = wm + mf * 16 + g;
                a[mf][0] = A[r * 36 + k8 + t4];
                a[mf][1] = A[(r + 8) * 36 + k8 + t4];
                a[mf][2] = A[r * 36 + k8 + t4 + 4];
                a[mf][3] = A[(r + 8) * 36 + k8 + t4 + 4];
            }
#pragma unroll
            for (int nt = 0; nt < 8; nt++) {
                uint32_t b0 = B[(wn + nt * 8 + g) * 36 + k8 + t4];
                uint32_t b1 = B[(wn + nt * 8 + g) * 36 + k8 + t4 + 4];
                mma_tf32(c[0][nt], a[0], b0, b1);
                mma_tf32(c[1][nt], a[1], b0, b1);
            }
        }
        __syncthreads();
    }

#pragma unroll
    for (int mf = 0; mf < 2; mf++) {
#pragma unroll
        for (int nt = 0; nt < 8; nt++) {
#pragma unroll
            for (int half = 0; half < 2; half++) {
                int m = m0 + wm + mf * 16 + g + half * 8;
                int b = m >> 6;
                int tt = m & 63;
                int n = n0 + wn + nt * 8 + (t4 << 1);
                float2 out;
                out.x = c[mf][nt][half * 2 + 0] + b_ih[n];
                out.y = c[mf][nt][half * 2 + 1] + b_ih[n + 1];
                *reinterpret_cast<float2*>(
                    &g_xg[((size_t)tt * NB + b) * N3H + n]) = out;
            }
        }
    }
}

// ---------------------------------------------------------------------------
// k_recur: PERSISTENT GRU recurrence, fp16 MMA, DATAFLOW synchronization.
// 128 CTAs = 32 unit-groups x 4 batch-quarters. No global barrier, no fences:
// producer (ug,bq) publishes g_flag[bq][ug]=t+1 with st.release after writing
// its h16 slice with st.cg; consumers poll with ld.acquire before cp.async.cg
// of each K-stage. h_old carried in registers (epilogue pairs == own output).
// ---------------------------------------------------------------------------
__global__ void __launch_bounds__(256)
k_recur(const int* __restrict__ slen, const float* __restrict__ w_hh,
        const float* __restrict__ b_hh) {
    extern __shared__ uint32_t sm[];
    uint32_t* sW = sm;                    // [96][SWW] (each word = 2 fp16)
    uint32_t* sH = sm + SWROWS * SWW;     // [NSTG][32][SHW]

    const int tid  = threadIdx.x;
    const int wid  = tid >> 5;
    const int lane = tid & 31;
    const int g    = lane >> 2;
    const int t4   = lane & 3;

    const int ug = blockIdx.x >> 2;       // unit group 0..31
    const int bq = blockIdx.x & 3;        // batch quarter 0..3
    const int j0 = ug * UCNT;
    const int b0 = bq * BROWS;

    const int bh = wid & 1;               // batch half (16 rows)
    const int uh = wid >> 1;              // unit octet (8 units)

    // ---- convert this CTA's 96 w_hh rows to fp16 in smem (once) ----
    for (int i = tid; i < SWROWS * 256; i += 256) {
        int r  = i >> 8;
        int c4 = (i & 255) << 2;
        int grow = (r >> 5) * NH + j0 + (r & 31);
        const float4 v = *reinterpret_cast<const float4*>(
            w_hh + (size_t)grow * NH + c4);
        __half2 p0 = __floats2half2_rn(v.x, v.y);
        __half2 p1 = __floats2half2_rn(v.z, v.w);
        uint32_t* d = sW + r * SWW + (c4 >> 1);
        d[0] = *reinterpret_cast<uint32_t*>(&p0);
        d[1] = *reinterpret_cast<uint32_t*>(&p1);
    }

    // ---- per-thread constants ----
    const int r0c = bh * 16 + g;
    const int r0g = b0 + r0c;
    const int r1g = r0g + 8;
    const int ja  = j0 + uh * 8 + (t4 << 1);
    const int len0 = slen[r0g] - 1;
    const int len1 = slen[r1g] - 1;
    const float bra = b_hh[ja],          brb = b_hh[ja + 1];
    const float bza = b_hh[NH + ja],     bzb = b_hh[NH + ja + 1];
    const float bna = b_hh[2 * NH + ja], bnb = b_hh[2 * NH + ja + 1];

    const int ldrow = tid >> 3;           // 0..31 (CTA-local row)
    const int ldcol = tid & 7;            // 16B chunk within 128B row-chunk

    // fp32 h state for this thread's (row,unit) pairs, carried in registers
    float2 hprev0 = make_float2(0.0f, 0.0f);
    float2 hprev1 = make_float2(0.0f, 0.0f);

    unsigned* myflag = &g_flag[bq][ug];
    const unsigned* qflags = &g_flag[bq][0];

    __syncthreads();   // sW ready

    for (int t = 0; t < NT; t++) {
        const __half* __restrict__ h16_in = g_h16[t & 1];
        __half* __restrict__ h16_out = g_h16[(t & 1) ^ 1];

        // ---- prefetch epilogue x-gate operands ----
        const float* xg0 = g_xg + ((size_t)t * NB + r0g) * N3H + ja;
        const float* xg1 = g_xg + ((size_t)t * NB + r1g) * N3H + ja;
        float2 xr0 = __ldg((const float2*)(xg0));
        float2 xz0 = __ldg((const float2*)(xg0 + NH));
        float2 xn0 = __ldg((const float2*)(xg0 + 2 * NH));
        float2 xr1 = __ldg((const float2*)(xg1));
        float2 xz1 = __ldg((const float2*)(xg1 + NH));
        float2 xn1 = __ldg((const float2*)(xg1 + 2 * NH));

        float c[3][4];
#pragma unroll
        for (int nt = 0; nt < 3; nt++)
#pragma unroll
            for (int e = 0; e < 4; e++) c[nt][e] = 0.0f;

        // ---- prologue: fill stages 0..NSTG-2 (with producer-flag waits) ----
#pragma unroll
        for (int s = 0; s < NSTG - 1; s++) {
            while (ld_acq(qflags + 2 * s)     < (unsigned)t) { }
            while (ld_acq(qflags + 2 * s + 1) < (unsigned)t) { }
            uint32_t sa = (uint32_t)__cvta_generic_to_shared(
                sH + s * STGW + ldrow * SHW + (ldcol << 2));
            cp_async16(sa, h16_in + (size_t)(b0 + ldrow) * NH + s * 64 + (ldcol << 3));
            cp_commit();
        }

        // ---- 16 stages of 64 halves each ----
        for (int it = 0; it < 16; it++) {
            cp_wait<NSTG - 2>();
            __syncthreads();

            const int nxt = it + NSTG - 1;
            if (nxt < 16) {
                while (ld_acq(qflags + 2 * nxt)     < (unsigned)t) { }
                while (ld_acq(qflags + 2 * nxt + 1) < (unsigned)t) { }
                uint32_t sa = (uint32_t)__cvta_generic_to_shared(
                    sH + (nxt % NSTG) * STGW + ldrow * SHW + (ldcol << 2));
                cp_async16(sa, h16_in + (size_t)(b0 + ldrow) * NH + nxt * 64 + (ldcol << 3));
            }
            cp_commit();               // empty group in tail keeps FIFO aligned

            const uint32_t* S = sH + (it % NSTG) * STGW;
            const int kw = it * 32;
#pragma unroll
            for (int kb = 0; kb < 32; kb += 8) {
                uint32_t a[4];
                a[0] = S[r0c * SHW + kb + t4];
                a[1] = S[(r0c + 8) * SHW + kb + t4];
                a[2] = S[r0c * SHW + kb + t4 + 4];
                a[3] = S[(r0c + 8) * SHW + kb + t4 + 4];
#pragma unroll
                for (int nt = 0; nt < 3; nt++) {
                    const uint32_t* W = sW + (nt * UCNT + uh * 8 + g) * SWW + kw + kb + t4;
                    mma_f16(c[nt], a, W[0], W[4]);
                }
            }
        }

        // ---- fused GRU gate epilogue ----
        {
            float hnew[4];
#pragma unroll
            for (int e = 0; e < 4; e++) {
                const int half = e >> 1;
                const int sub  = e & 1;
                float xr = half ? (sub ? xr1.y : xr1.x) : (sub ? xr0.y : xr0.x);
                float xz = half ? (sub ? xz1.y : xz1.x) : (sub ? xz0.y : xz0.x);
                float xn = half ? (sub ? xn1.y : xn1.x) : (sub ? xn0.y : xn0.x);
                float ho = half ? (sub ? hprev1.y : hprev1.x)
                                : (sub ? hprev0.y : hprev0.x);
                float hr = c[0][e] + (sub ? brb : bra);
                float hz = c[1][e] + (sub ? bzb : bza);
                float hn = c[2][e] + (sub ? bnb : bna);
                float rr = 1.0f / (1.0f + expf(-(xr + hr)));
                float zz = 1.0f / (1.0f + expf(-(xz + hz)));
                float nn = tanhf(xn + rr * hn);
                hnew[e] = (1.0f - zz) * nn + zz * ho;
            }
            hprev0 = make_float2(hnew[0], hnew[1]);
            hprev1 = make_float2(hnew[2], hnew[3]);
            __half2 p0 = __floats2half2_rn(hnew[0], hnew[1]);
            __half2 p1 = __floats2half2_rn(hnew[2], hnew[3]);
            __stcg((__half2*)(h16_out + (size_t)r0g * NH + ja), p0);
            __stcg((__half2*)(h16_out + (size_t)r1g * NH + ja), p1);
            if (len0 == t)
                *(float2*)(g_final + (size_t)r0g * NH + ja) = make_float2(hnew[0], hnew[1]);
            if (len1 == t)
                *(float2*)(g_final + (size_t)r1g * NH + ja) = make_float2(hnew[2], hnew[3]);
        }

        // ---- publish: all h16 stores done -> release flag ----
        __syncthreads();
        if (tid == 0) st_rel(myflag, (unsigned)(t + 1));
    }
}

// ---------------------------------------------------------------------------
// k_norm: L2-normalize each final row, write output
// ---------------------------------------------------------------------------
__global__ void __launch_bounds__(256)
k_norm(float* __restrict__ out) {
    const int b = blockIdx.x;
    const int tid = threadIdx.x;
    float s = 0.0f;
    for (int j = tid; j < NH; j += 256) {
        float v = g_final[(size_t)b * NH + j];
        s += v * v;
    }
#pragma unroll
    for (int o = 16; o; o >>= 1) s += __shfl_xor_sync(0xFFFFFFFFu, s, o);
    __shared__ float ws[8];
    __shared__ float s_norm;
    if ((tid & 31) == 0) ws[tid >> 5] = s;
    __syncthreads();
    if (tid == 0) {
        float x = 0.0f;
#pragma unroll
        for (int i = 0; i < 8; i++) x += ws[i];
        s_norm = sqrtf(x);
    }
    __syncthreads();
    float inv = 1.0f / s_norm;
    for (int j = tid; j < NH; j += 256)
        out[(size_t)b * NH + j] = g_final[(size_t)b * NH + j] * inv;
}

// ---------------------------------------------------------------------------
// entry point
// ---------------------------------------------------------------------------
extern "C" void kernel_launch(void* const* d_in, const int* in_sizes, int n_in,
                              void* d_out, int out_size) {
    const int*   sent  = (const int*)d_in[0];
    const int*   slen  = (const int*)d_in[1];
    const float* emb   = (const float*)d_in[2];
    const float* w_ih  = (const float*)d_in[3];
    const float* w_hh  = (const float*)d_in[4];
    const float* b_ih  = (const float*)d_in[5];
    const float* b_hh  = (const float*)d_in[6];

    const int smem_xg    = 2 * 2 * 128 * 36 * 4;                    // 73,728 B
    const int smem_recur = (SWROWS * SWW + NSTG * STGW) * 4;        // 225,792 B
    cudaFuncSetAttribute(k_xgates, cudaFuncAttributeMaxDynamicSharedMemorySize,
                         smem_xg);
    cudaFuncSetAttribute(k_recur, cudaFuncAttributeMaxDynamicSharedMemorySize,
                         smem_recur);

    k_init<<<512, 256>>>();
    k_xgates<<<dim3(N3H / 128, NBT / 128), 256, smem_xg>>>(sent, emb, w_ih, b_ih);
    k_recur<<<128, 256, smem_recur>>>(slen, w_hh, b_hh);
    k_norm<<<NB, 256>>>((float*)d_out);
}

// round 6
// speedup vs baseline: 2.5533x; 2.5533x over previous
#include <cuda_runtime.h>
#include <cuda_fp16.h>
#include <cuda_bf16.h>
#include <cstdint>

// Problem constants
#define NB   128          // batch
#define NT   64           // max timesteps
#define NE   512          // embedding dim
#define NH   1024         // hidden dim
#define N3H  3072         // 3*H (gate order r,z,n)
#define NBT  (NB*NT)      // 8192 rows for xgates GEMM

// k_recur geometry: each CTA owns 32 units x 32 batch rows
#define UCNT   32                 // hidden units per CTA
#define BROWS  32                 // batch rows per CTA
#define SWROWS 96                 // 3 gates * 32 units
#define SWW    516                // w_hh row stride (512 words = 1024 fp16) + 4 pad
#define SHW    68                 // h stage row stride: 64 words (128 fp16) + 4 pad
#define NSTG   3                  // cp.async ring depth
#define STGW   (BROWS * SHW)      // words per stage (2176)

// Scratch (device globals; no runtime allocation allowed)
__device__ float g_xg[(size_t)NT * NB * N3H];              // [t][b][3H]
__device__ __align__(16) __half g_h16[2][NB * NH];         // fp16 h exchange (L2)
__device__ __align__(16) __half g_a16[(size_t)NBT * NE];   // gathered emb, fp16
__device__ __align__(16) __half g_w16[(size_t)N3H * NE];   // w_ih, fp16
__device__ float g_final[NB * NH];                         // h at t == len-1
__device__ unsigned g_qf[4][32][8];                        // [bq][ug] flags, 32B spaced

// ---------------------------------------------------------------------------
// helpers
// ---------------------------------------------------------------------------
__device__ __forceinline__ void mma_f16(float c[4], const uint32_t a[4],
                                        uint32_t b0, uint32_t b1) {
    asm volatile(
        "mma.sync.aligned.m16n8k16.row.col.f32.f16.f16.f32 "
        "{%0,%1,%2,%3}, {%4,%5,%6,%7}, {%8,%9}, {%0,%1,%2,%3};"
        : "+f"(c[0]), "+f"(c[1]), "+f"(c[2]), "+f"(c[3])
        : "r"(a[0]), "r"(a[1]), "r"(a[2]), "r"(a[3]), "r"(b0), "r"(b1));
}

__device__ __forceinline__ void cp_async16(uint32_t saddr, const void* gaddr) {
    asm volatile("cp.async.cg.shared.global [%0], [%1], 16;"
                 :: "r"(saddr), "l"(gaddr));
}
__device__ __forceinline__ void cp_commit() {
    asm volatile("cp.async.commit_group;");
}
template <int N>
__device__ __forceinline__ void cp_wait() {
    asm volatile("cp.async.wait_group %0;" :: "n"(N));
}

__device__ __forceinline__ unsigned ld_acq(const unsigned* p) {
    unsigned v;
    asm volatile("ld.acquire.gpu.global.u32 %0, [%1];" : "=r"(v) : "l"(p));
    return v;
}
__device__ __forceinline__ void st_rel(unsigned* p, unsigned v) {
    asm volatile("st.release.gpu.global.u32 [%0], %1;" :: "l"(p), "r"(v));
}

// ---------------------------------------------------------------------------
// k_init: zero h16[0] and flags
// ---------------------------------------------------------------------------
__global__ void k_init() {
    int i = blockIdx.x * blockDim.x + threadIdx.x;
    if (i < NB * NH) g_h16[0][i] = __float2half(0.0f);
    if (i < 4 * 32 * 8) ((unsigned*)g_qf)[i] = 0u;
}

// ---------------------------------------------------------------------------
// k_cvt: gather emb rows per (b,t) token and convert to fp16; convert w_ih.
// grid = NBT + N3H rows, 128 threads/row (512 floats per row).
// ---------------------------------------------------------------------------
__global__ void __launch_bounds__(128)
k_cvt(const int* __restrict__ sent, const float* __restrict__ emb,
      const float* __restrict__ w_ih) {
    const int row = blockIdx.x;
    const int tid = threadIdx.x;
    const float* src;
    __half* dst;
    if (row < NBT) {
        src = emb + (size_t)sent[row] * NE;
        dst = g_a16 + (size_t)row * NE;
    } else {
        src = w_ih + (size_t)(row - NBT) * NE;
        dst = g_w16 + (size_t)(row - NBT) * NE;
    }
    const float4 v = reinterpret_cast<const float4*>(src)[tid];
    __half2 p0 = __floats2half2_rn(v.x, v.y);
    __half2 p1 = __floats2half2_rn(v.z, v.w);
    uint2 u;
    u.x = *reinterpret_cast<uint32_t*>(&p0);
    u.y = *reinterpret_cast<uint32_t*>(&p1);
    reinterpret_cast<uint2*>(dst)[tid] = u;
}

// ---------------------------------------------------------------------------
// k_xgates: fp16 GEMM. xg[t][b][n] = a16[m] . w16[n] + b_ih[n]
// M=8192, N=3072, K=512. Tile 128x128, KC=64 halves, double-buffered cp.async.
// Dynamic smem: 2 stages x (A 128x36 + B 128x36) words = 73,728 B.
// ---------------------------------------------------------------------------
__global__ void __launch_bounds__(256, 2)
k_xgates(const float* __restrict__ b_ih) {
    extern __shared__ uint32_t xsm[];
    uint32_t* sA = xsm;                    // [2][128][36]
    uint32_t* sB = xsm + 2 * 128 * 36;     // [2][128][36]

    const int tid  = threadIdx.x;
    const int wid  = tid >> 5;
    const int lane = tid & 31;
    const int g    = lane >> 2;
    const int t4   = lane & 3;

    const int m0 = blockIdx.y * 128;
    const int n0 = blockIdx.x * 128;
    const int wm = (wid & 3) * 32;
    const int wn = (wid >> 2) * 64;

    // per-thread load coordinates: 4 chunks of 16B (8 halves) per array
    int ldrow[4], ldc16[4];
#pragma unroll
    for (int p = 0; p < 4; p++) {
        int idx = tid + p * 256;
        ldrow[p] = idx >> 3;           // 0..127
        ldc16[p] = idx & 7;            // 16B chunk within 128B
    }

    float c[2][8][4];
#pragma unroll
    for (int mf = 0; mf < 2; mf++)
#pragma unroll
        for (int nt = 0; nt < 8; nt++)
#pragma unroll
            for (int e = 0; e < 4; e++) c[mf][nt][e] = 0.0f;

    // prologue: stage 0 <- ktile 0
#pragma unroll
    for (int p = 0; p < 4; p++) {
        uint32_t sa = (uint32_t)__cvta_generic_to_shared(
            sA + ldrow[p] * 36 + ldc16[p] * 4);
        cp_async16(sa, g_a16 + (size_t)(m0 + ldrow[p]) * NE + ldc16[p] * 8);
        uint32_t sb = (uint32_t)__cvta_generic_to_shared(
            sB + ldrow[p] * 36 + ldc16[p] * 4);
        cp_async16(sb, g_w16 + (size_t)(n0 + ldrow[p]) * NE + ldc16[p] * 8);
    }
    cp_commit();

    for (int kt = 0; kt < 8; kt++) {
        const int cur = kt & 1;
        if (kt + 1 < 8) {
            const int nxt = cur ^ 1;
            const int kk = (kt + 1) * 64;   // halves
#pragma unroll
            for (int p = 0; p < 4; p++) {
                uint32_t sa = (uint32_t)__cvta_generic_to_shared(
                    sA + nxt * 128 * 36 + ldrow[p] * 36 + ldc16[p] * 4);
                cp_async16(sa, g_a16 + (size_t)(m0 + ldrow[p]) * NE + kk + ldc16[p] * 8);
                uint32_t sb = (uint32_t)__cvta_generic_to_shared(
                    sB + nxt * 128 * 36 + ldrow[p] * 36 + ldc16[p] * 4);
                cp_async16(sb, g_w16 + (size_t)(n0 + ldrow[p]) * NE + kk + ldc16[p] * 8);
            }
        }
        cp_commit();
        cp_wait<1>();
        __syncthreads();

        const uint32_t* A = sA + cur * 128 * 36;
        const uint32_t* B = sB + cur * 128 * 36;
#pragma unroll
        for (int kb = 0; kb < 32; kb += 8) {    // 4 k16 blocks (words)
            uint32_t a[2][4];
#pragma unroll
            for (int mf = 0; mf < 2; mf++) {
                int r = wm + mf * 16 + g;
                a[mf][0] = A[r * 36 + kb + t4];
                a[mf][1] = A[(r + 8) * 36 + kb + t4];
                a[mf][2] = A[r * 36 + kb + t4 + 4];
                a[mf][3] = A[(r + 8) * 36 + kb + t4 + 4];
            }
#pragma unroll
            for (int nt = 0; nt < 8; nt++) {
                uint32_t b0 = B[(wn + nt * 8 + g) * 36 + kb + t4];
                uint32_t b1 = B[(wn + nt * 8 + g) * 36 + kb + t4 + 4];
                mma_f16(c[0][nt], a[0], b0, b1);
                mma_f16(c[1][nt], a[1], b0, b1);
            }
        }
        __syncthreads();
    }

#pragma unroll
    for (int mf = 0; mf < 2; mf++) {
#pragma unroll
        for (int nt = 0; nt < 8; nt++) {
#pragma unroll
            for (int half = 0; half < 2; half++) {
                int m = m0 + wm + mf * 16 + g + half * 8;
                int b = m >> 6;
                int tt = m & 63;
                int n = n0 + wn + nt * 8 + (t4 << 1);
                float2 out;
                out.x = c[mf][nt][half * 2 + 0] + __ldg(b_ih + n);
                out.y = c[mf][nt][half * 2 + 1] + __ldg(b_ih + n + 1);
                *reinterpret_cast<float2*>(
                    &g_xg[((size_t)tt * NB + b) * N3H + n]) = out;
            }
        }
    }
}

// ---------------------------------------------------------------------------
// k_recur: PERSISTENT GRU recurrence, fp16 MMA, quarter-local flag barrier.
// 128 CTAs = 32 unit-groups x 4 batch-quarters. h exchange stays within a
// quarter (32 CTAs): at step start, warp-0 lanes each poll one producer flag
// (ld.acquire); at step end, tid0 publishes with fence + st.release.
// 8 K-stages of 128 halves, cp.async ring depth 3. h_old in registers.
// Dynamic smem = 96*516 + 3*2176 words = 224,256 B.
// ---------------------------------------------------------------------------
__global__ void __launch_bounds__(256)
k_recur(const int* __restrict__ slen, const float* __restrict__ w_hh,
        const float* __restrict__ b_hh) {
    extern __shared__ uint32_t sm[];
    uint32_t* sW = sm;                    // [96][SWW] (each word = 2 fp16)
    uint32_t* sH = sm + SWROWS * SWW;     // [NSTG][32][SHW]

    const int tid  = threadIdx.x;
    const int wid  = tid >> 5;
    const int lane = tid & 31;
    const int g    = lane >> 2;
    const int t4   = lane & 3;

    const int ug = blockIdx.x >> 2;       // unit group 0..31
    const int bq = blockIdx.x & 3;        // batch quarter 0..3
    const int j0 = ug * UCNT;
    const int b0 = bq * BROWS;

    const int bh = wid & 1;               // batch half (16 rows)
    const int uh = wid >> 1;              // unit octet (8 units)

    // ---- convert this CTA's 96 w_hh rows to fp16 in smem (once) ----
    for (int i = tid; i < SWROWS * 256; i += 256) {
        int r  = i >> 8;
        int c4 = (i & 255) << 2;
        int grow = (r >> 5) * NH + j0 + (r & 31);
        const float4 v = *reinterpret_cast<const float4*>(
            w_hh + (size_t)grow * NH + c4);
        __half2 p0 = __floats2half2_rn(v.x, v.y);
        __half2 p1 = __floats2half2_rn(v.z, v.w);
        uint32_t* d = sW + r * SWW + (c4 >> 1);
        d[0] = *reinterpret_cast<uint32_t*>(&p0);
        d[1] = *reinterpret_cast<uint32_t*>(&p1);
    }

    // ---- per-thread constants ----
    const int r0c = bh * 16 + g;
    const int r0g = b0 + r0c;
    const int r1g = r0g + 8;
    const int ja  = j0 + uh * 8 + (t4 << 1);
    const int len0 = slen[r0g] - 1;
    const int len1 = slen[r1g] - 1;
    const float bra = b_hh[ja],          brb = b_hh[ja + 1];
    const float bza = b_hh[NH + ja],     bzb = b_hh[NH + ja + 1];
    const float bna = b_hh[2 * NH + ja], bnb = b_hh[2 * NH + ja + 1];

    // cp.async coordinates: 2 chunks of 16B per thread per stage
    const int ldrow = tid >> 4;           // 0..15 (+16 for second chunk)
    const int ldc16 = tid & 15;           // 16B chunk within 256B row-stage

    // fp32 h state carried in registers
    float2 hprev0 = make_float2(0.0f, 0.0f);
    float2 hprev1 = make_float2(0.0f, 0.0f);

    __syncthreads();   // sW ready

    for (int t = 0; t < NT; t++) {
        const __half* __restrict__ h16_in = g_h16[t & 1];
        __half* __restrict__ h16_out = g_h16[(t & 1) ^ 1];

        // ---- quarter-local wait: all 32 producers of my quarter at step t ----
        if (tid < 32) {
            while (ld_acq(&g_qf[bq][tid][0]) < (unsigned)t) { }
        }
        __syncthreads();

        // ---- prefetch epilogue x-gate operands ----
        const float* xg0 = g_xg + ((size_t)t * NB + r0g) * N3H + ja;
        const float* xg1 = g_xg + ((size_t)t * NB + r1g) * N3H + ja;
        float2 xr0 = __ldg((const float2*)(xg0));
        float2 xz0 = __ldg((const float2*)(xg0 + NH));
        float2 xn0 = __ldg((const float2*)(xg0 + 2 * NH));
        float2 xr1 = __ldg((const float2*)(xg1));
        float2 xz1 = __ldg((const float2*)(xg1 + NH));
        float2 xn1 = __ldg((const float2*)(xg1 + 2 * NH));

        float c[3][4];
#pragma unroll
        for (int nt = 0; nt < 3; nt++)
#pragma unroll
            for (int e = 0; e < 4; e++) c[nt][e] = 0.0f;

        // ---- prologue: fill stages 0,1 ----
#pragma unroll
        for (int s = 0; s < NSTG - 1; s++) {
            uint32_t* dst = sH + s * STGW;
#pragma unroll
            for (int p = 0; p < 2; p++) {
                int rr = ldrow + p * 16;
                uint32_t sa = (uint32_t)__cvta_generic_to_shared(
                    dst + rr * SHW + ldc16 * 4);
                cp_async16(sa, h16_in + (size_t)(b0 + rr) * NH + s * 128 + ldc16 * 8);
            }
            cp_commit();
        }

        // ---- 8 stages of 128 halves each ----
        for (int it = 0; it < 8; it++) {
            cp_wait<1>();
            __syncthreads();

            const int nxt = it + 2;
            if (nxt < 8) {
                uint32_t* dst = sH + (nxt % NSTG) * STGW;
#pragma unroll
                for (int p = 0; p < 2; p++) {
                    int rr = ldrow + p * 16;
                    uint32_t sa = (uint32_t)__cvta_generic_to_shared(
                        dst + rr * SHW + ldc16 * 4);
                    cp_async16(sa, h16_in + (size_t)(b0 + rr) * NH + nxt * 128 + ldc16 * 8);
                }
            }
            cp_commit();               // empty group in tail keeps FIFO aligned

            const uint32_t* S = sH + (it % NSTG) * STGW;
            const int kw = it * 64;    // word offset into sW rows
#pragma unroll
            for (int kb = 0; kb < 64; kb += 8) {
                uint32_t a[4];
                a[0] = S[r0c * SHW + kb + t4];
                a[1] = S[(r0c + 8) * SHW + kb + t4];
                a[2] = S[r0c * SHW + kb + t4 + 4];
                a[3] = S[(r0c + 8) * SHW + kb + t4 + 4];
#pragma unroll
                for (int nt = 0; nt < 3; nt++) {
                    const uint32_t* W = sW + (nt * UCNT + uh * 8 + g) * SWW + kw + kb + t4;
                    mma_f16(c[nt], a, W[0], W[4]);
                }
            }
        }

        // ---- fused GRU gate epilogue ----
        {
            float hnew[4];
#pragma unroll
            for (int e = 0; e < 4; e++) {
                const int half = e >> 1;
                const int sub  = e & 1;
                float xr = half ? (sub ? xr1.y : xr1.x) : (sub ? xr0.y : xr0.x);
                float xz = half ? (sub ? xz1.y : xz1.x) : (sub ? xz0.y : xz0.x);
                float xn = half ? (sub ? xn1.y : xn1.x) : (sub ? xn0.y : xn0.x);
                float ho = half ? (sub ? hprev1.y : hprev1.x)
                                : (sub ? hprev0.y : hprev0.x);
                float hr = c[0][e] + (sub ? brb : bra);
                float hz = c[1][e] + (sub ? bzb : bza);
                float hn = c[2][e] + (sub ? bnb : bna);
                float rr = 1.0f / (1.0f + expf(-(xr + hr)));
                float zz = 1.0f / (1.0f + expf(-(xz + hz)));
                float nn = tanhf(xn + rr * hn);
                hnew[e] = (1.0f - zz) * nn + zz * ho;
            }
            hprev0 = make_float2(hnew[0], hnew[1]);
            hprev1 = make_float2(hnew[2], hnew[3]);
            __half2 p0 = __floats2half2_rn(hnew[0], hnew[1]);
            __half2 p1 = __floats2half2_rn(hnew[2], hnew[3]);
            __stcg((__half2*)(h16_out + (size_t)r0g * NH + ja), p0);
            __stcg((__half2*)(h16_out + (size_t)r1g * NH + ja), p1);
            if (len0 == t)
                *(float2*)(g_final + (size_t)r0g * NH + ja) = make_float2(hnew[0], hnew[1]);
            if (len1 == t)
                *(float2*)(g_final + (size_t)r1g * NH + ja) = make_float2(hnew[2], hnew[3]);
        }

        // ---- publish ----
        __syncthreads();
        if (tid == 0) {
            asm volatile("fence.acq_rel.gpu;" ::: "memory");
            st_rel(&g_qf[bq][ug][0], (unsigned)(t + 1));
        }
    }
}

// ---------------------------------------------------------------------------
// k_norm: L2-normalize each final row, write output
// ---------------------------------------------------------------------------
__global__ void __launch_bounds__(256)
k_norm(float* __restrict__ out) {
    const int b = blockIdx.x;
    const int tid = threadIdx.x;
    float s = 0.0f;
    for (int j = tid; j < NH; j += 256) {
        float v = g_final[(size_t)b * NH + j];
        s += v * v;
    }
#pragma unroll
    for (int o = 16; o; o >>= 1) s += __shfl_xor_sync(0xFFFFFFFFu, s, o);
    __shared__ float ws[8];
    __shared__ float s_norm;
    if ((tid & 31) == 0) ws[tid >> 5] = s;
    __syncthreads();
    if (tid == 0) {
        float x = 0.0f;
#pragma unroll
        for (int i = 0; i < 8; i++) x += ws[i];
        s_norm = sqrtf(x);
    }
    __syncthreads();
    float inv = 1.0f / s_norm;
    for (int j = tid; j < NH; j += 256)
        out[(size_t)b * NH + j] = g_final[(size_t)b * NH + j] * inv;
}

// ---------------------------------------------------------------------------
// entry point
// ---------------------------------------------------------------------------
extern "C" void kernel_launch(void* const* d_in, const int* in_sizes, int n_in,
                              void* d_out, int out_size) {
    const int*   sent  = (const int*)d_in[0];
    const int*   slen  = (const int*)d_in[1];
    const float* emb   = (const float*)d_in[2];
    const float* w_ih  = (const float*)d_in[3];
    const float* w_hh  = (const float*)d_in[4];
    const float* b_ih  = (const float*)d_in[5];
    const float* b_hh  = (const float*)d_in[6];

    const int smem_xg    = 2 * 2 * 128 * 36 * 4;                    // 73,728 B
    const int smem_recur = (SWROWS * SWW + NSTG * STGW) * 4;        // 224,256 B
    cudaFuncSetAttribute(k_xgates, cudaFuncAttributeMaxDynamicSharedMemorySize,
                         smem_xg);
    cudaFuncSetAttribute(k_recur, cudaFuncAttributeMaxDynamicSharedMemorySize,
                         smem_recur);

    k_init<<<512, 256>>>();
    k_cvt<<<NBT + N3H, 128>>>(sent, emb, w_ih);
    k_xgates<<<dim3(N3H / 128, NBT / 128), 256, smem_xg>>>(b_ih);
    k_recur<<<128, 256, smem_recur>>>(slen, w_hh, b_hh);
    k_norm<<<NB, 256>>>((float*)d_out);
}